// round 16
// baseline (speedup 1.0000x reference)
#include <cuda_runtime.h>
#include <cstdint>
#include <cstddef>

// ---------------- problem constants ----------------
#define D      1024
#define BATCH  32
#define NELEM  ((size_t)BATCH * D * D)

// ---------------- tiling ----------------
#define BM 128
#define BN 128
#define BK 32
#define STAGES 3
#define A_STAGE ((BM / 16) * (BK / 8) * 32 * 16)   // 16384 bytes
#define B_STAGE ((BN / 8) * (BK / 16) * 32 * 16)   // 16384 bytes
#define STAGE_BYTES (A_STAGE + B_STAGE)            // 32768
#define SMEM_BYTES (STAGES * STAGE_BYTES)          // 98304 -> 2 CTAs/SM
#define SZP 136                                    // epilogue staging stride (floats)
#define NTHREADS 128

// ---------------- device scratch (allocation-free) ----------------
__device__ __align__(16) unsigned g_PA[3u * 1024 * 1024];   // Wp | W3 | W4 (A-frag tf32)
__device__ __align__(16) unsigned g_PQ[NELEM];              // Q  (B-frag tf32)
__device__ __align__(16) unsigned g_PM[NELEM];              // M  (B-frag tf32)
__device__ __align__(16) unsigned g_Pq[NELEM];              // q  (B-frag tf32)
__device__ __align__(16) float    g_q [NELEM];              // exact q (gate)

// ---------------- helpers ----------------
__device__ __forceinline__ unsigned f2tf32(float x) {
    unsigned r; asm("cvt.rna.tf32.f32 %0, %1;" : "=r"(r) : "f"(x)); return r;
}
__device__ __forceinline__ uint32_t smem_u32(const void* p) {
    uint32_t a;
    asm("{ .reg .u64 t; cvta.to.shared.u64 t, %1; cvt.u32.u64 %0, t; }" : "=r"(a) : "l"(p));
    return a;
}
__device__ __forceinline__ void cp16(uint32_t daddr, const void* src) {
    asm volatile("cp.async.cg.shared.global [%0], [%1], 16;\n" :: "r"(daddr), "l"(src));
}
__device__ __forceinline__ void cp_commit() { asm volatile("cp.async.commit_group;\n" ::); }
__device__ __forceinline__ void cp_wait1()  { asm volatile("cp.async.wait_group 1;\n" ::); }

__device__ __forceinline__ uint4 lds128(uint32_t addr) {
    uint4 v;
    asm volatile("ld.shared.v4.u32 {%0,%1,%2,%3}, [%4];"
                 : "=r"(v.x), "=r"(v.y), "=r"(v.z), "=r"(v.w) : "r"(addr));
    return v;
}
__device__ __forceinline__ void mma_tf32(float c[4], uint4 a, unsigned b0, unsigned b1) {
    asm volatile(
        "mma.sync.aligned.m16n8k8.row.col.f32.tf32.tf32.f32 "
        "{%0,%1,%2,%3}, {%4,%5,%6,%7}, {%8,%9}, {%0,%1,%2,%3};\n"
        : "+f"(c[0]), "+f"(c[1]), "+f"(c[2]), "+f"(c[3])
        : "r"(a.x), "r"(a.y), "r"(a.z), "r"(a.w), "r"(b0), "r"(b1));
}

// ---------------- pre-permutation kernels ----------------
// A-frag order: PA[mblk(64)][kblk(128)][lane(32)][4], tf32 bits. (3 weights fused)
__global__ void permA3_kernel(const float* __restrict__ W0, const float* __restrict__ W1,
                              const float* __restrict__ W2, unsigned* __restrict__ PA) {
    const float* W = (blockIdx.y == 0) ? W0 : (blockIdx.y == 1) ? W1 : W2;
    unsigned* P = PA + ((size_t)blockIdx.y << 20);
    int t = blockIdx.x * blockDim.x + threadIdx.x;
    int lane = t & 31, kblk = (t >> 5) & 127, mblk = t >> 12;
    int g = lane >> 2, tg = lane & 3;
    int m0 = mblk * 16 + g, k0 = kblk * 8 + tg;
    uint4 o;
    o.x = f2tf32(W[(size_t)m0 * D + k0]);
    o.y = f2tf32(W[(size_t)(m0 + 8) * D + k0]);
    o.z = f2tf32(W[(size_t)m0 * D + k0 + 4]);
    o.w = f2tf32(W[(size_t)(m0 + 8) * D + k0 + 4]);
    reinterpret_cast<uint4*>(P)[t] = o;
}

// B-frag order for BOTH Q and M in one launch: grid.y 0..31 -> Q, 32..63 -> M.
__global__ void permB2_kernel(const float* __restrict__ Q, const float* __restrict__ M,
                              unsigned* __restrict__ PQ, unsigned* __restrict__ PM) {
    const int yy = blockIdx.y;
    const int b = yy & 31;
    const float* Xb = ((yy < 32) ? Q : M) + (size_t)b * D * D;
    unsigned* PB = ((yy < 32) ? PQ : PM);
    int t = blockIdx.x * blockDim.x + threadIdx.x;
    int lane = t & 31, k16 = (t >> 5) & 63, nblk = t >> 11;
    int g = lane >> 2, tg = lane & 3;
    int n = nblk * 8 + g, k0 = k16 * 16 + tg;
    uint4 o;
    o.x = f2tf32(Xb[(size_t)k0 * D + n]);
    o.y = f2tf32(Xb[(size_t)(k0 + 4) * D + n]);
    o.z = f2tf32(Xb[(size_t)(k0 + 8) * D + n]);
    o.w = f2tf32(Xb[(size_t)(k0 + 12) * D + n]);
    reinterpret_cast<uint4*>(PB + (size_t)b * D * D)[t] = o;
}

// ---------------- main GEMM ----------------
// 128x128 CTA tile, 4 warps (64x64 each, 2x2 grid), BK=32, 3-stage cp.async,
// 2 CTAs/SM. chunks 0..SPLIT-1 use (A0,B0); SPLIT..KT-1 use (A1,B1).
// MODE 0: g_q = acc + bias (exact); g_Pq = tf32 B-frag order via smem staging
// MODE 1: out = relu(acc + bias) * g_q
template <int MODE, int KT, int SPLIT>
__global__ void __launch_bounds__(NTHREADS, 2)
gemm_tf32(const unsigned* __restrict__ A0, const unsigned* __restrict__ B0,
          const unsigned* __restrict__ A1, const unsigned* __restrict__ B1,
          const float* __restrict__ bias, float* __restrict__ outp) {
    extern __shared__ char smem[];
    const uint32_t sbase = smem_u32(smem);

    const int tid  = threadIdx.x;
    const int lane = tid & 31;
    const int wid  = tid >> 5;     // 0..3

    const int b      = blockIdx.z;
    const int bmblk  = blockIdx.y * (BM / 16);   // 8 mblk per tile
    const int bnblk  = blockIdx.x * (BN / 8);    // 16 nblk per tile
    const size_t boff = (size_t)b * D * D;

    const char* PBb0 = (const char*)(B0 + boff);
    const char* PBb1 = (const char*)(B1 + boff);

    float acc[4][8][4];
#pragma unroll
    for (int mt = 0; mt < 4; mt++)
#pragma unroll
        for (int nt = 0; nt < 8; nt++)
#pragma unroll
            for (int i = 0; i < 4; i++) acc[mt][nt][i] = 0.0f;

    // loader mapping: 128 threads; A = 1024 uint4 (8/thread), B = 1024 uint4 (8/thread)
    auto load_chunk = [&](int c) {
        const int s = c % STAGES;
        const uint32_t sa = sbase + s * STAGE_BYTES;
        const uint32_t sb = sa + A_STAGE;
        const char* Abase; const char* Bbase; int cc;
        if (c < SPLIT) { Abase = (const char*)A0; Bbase = PBb0; cc = c; }
        else           { Abase = (const char*)A1; Bbase = PBb1; cc = c - SPLIT; }
#pragma unroll
        for (int i = 0; i < 8; i++) {
            const unsigned o = tid * 16 + i * 2048;        // byte offset in 16KB A stage
            const int mb = o >> 11;                        // 2KB contiguous per mblk
            const unsigned rest = o & 2047;
            cp16(sa + o, Abase + (((size_t)(bmblk + mb) * 128 + cc * 4) << 9) + rest);
        }
#pragma unroll
        for (int i = 0; i < 8; i++) {
            const unsigned o = tid * 16 + i * 2048;        // byte offset in 16KB B stage
            const int nb = o >> 10;                        // 1KB contiguous per nblk
            const unsigned rest = o & 1023;
            cp16(sb + o, Bbase + (((size_t)(bnblk + nb) * 64 + cc * 2) << 9) + rest);
        }
    };

    const int wm4 = (wid >> 1) * 4;   // mblk base (2 row groups of warps)
    const int wn8 = (wid & 1) * 8;    // nblk base (2 col groups of warps)
    const uint32_t laneoff = lane * 16;

    auto compute_chunk = [&](int c) {
        const uint32_t sa = sbase + (c % STAGES) * STAGE_BYTES;
        const uint32_t sb = sa + A_STAGE;
#pragma unroll
        for (int k16 = 0; k16 < 2; k16++) {
            uint4 bfr[8];
#pragma unroll
            for (int nt = 0; nt < 8; nt++)
                bfr[nt] = lds128(sb + (wn8 + nt) * 1024 + k16 * 512 + laneoff);
#pragma unroll
            for (int half = 0; half < 2; half++) {
                uint4 afr[4];
#pragma unroll
                for (int mt = 0; mt < 4; mt++)
                    afr[mt] = lds128(sa + (wm4 + mt) * 2048 + (k16 * 2 + half) * 512 + laneoff);
#pragma unroll
                for (int nt = 0; nt < 8; nt++) {
                    const unsigned b0 = half ? bfr[nt].z : bfr[nt].x;
                    const unsigned b1 = half ? bfr[nt].w : bfr[nt].y;
#pragma unroll
                    for (int mt = 0; mt < 4; mt++)
                        mma_tf32(acc[mt][nt], afr[mt], b0, b1);
                }
            }
        }
    };

    // prologue: fill 3 stages
    load_chunk(0); cp_commit();
    load_chunk(1); cp_commit();
    load_chunk(2); cp_commit();

    // pair-wise mainloop, 3 stages: compute (c0, c0+1) while c0+2 is in flight
    for (int t = 0; t < KT / 2; t++) {
        const int c0 = 2 * t;
        cp_wait1();            // chunks c0, c0+1 complete (newest group may fly)
        __syncthreads();

        compute_chunk(c0);
        compute_chunk(c0 + 1);

        __syncthreads();       // all warps done reading stages (c0, c0+1)
        if (c0 + 3 < KT) load_chunk(c0 + 3);   // targets stage (c0) % 3
        cp_commit();
        if (c0 + 4 < KT) load_chunk(c0 + 4);   // targets stage (c0+1) % 3
        cp_commit();
    }

    // ---------------- epilogue ----------------
    const int g  = lane >> 2;
    const int tg = lane & 3;
    const int bm = blockIdx.y * BM;
    const int bn = blockIdx.x * BN;
    const int wm = (wid >> 1) * 64;
    const int wn = (wid & 1) * 64;

    if (MODE == 0) {
        // stage z-tile (bias added) into smem; stage buffers are dead now
        __syncthreads();
        float* zs = reinterpret_cast<float*>(smem);   // 128 x SZP floats = 69.6KB < 96KB
#pragma unroll
        for (int mt = 0; mt < 4; mt++) {
#pragma unroll
            for (int nt = 0; nt < 8; nt++) {
                const int rl = wm + mt * 16 + g;
                const int cl = wn + nt * 8 + 2 * tg;
                const int col = bn + cl;
                const float bv0 = __ldg(bias + col);
                const float bv1 = __ldg(bias + col + 1);
                const float z0 = acc[mt][nt][0] + bv0;
                const float z1 = acc[mt][nt][1] + bv1;
                const float z2 = acc[mt][nt][2] + bv0;
                const float z3 = acc[mt][nt][3] + bv1;
                zs[rl * SZP + cl] = z0;
                zs[rl * SZP + cl + 1] = z1;
                zs[(rl + 8) * SZP + cl] = z2;
                zs[(rl + 8) * SZP + cl + 1] = z3;
                // exact q
                const int row = bm + rl;
                const size_t i0 = boff + (size_t)row * D + col;
                const size_t i1 = i0 + (size_t)8 * D;
                *reinterpret_cast<float2*>(g_q + i0) = make_float2(z0, z1);
                *reinterpret_cast<float2*>(g_q + i1) = make_float2(z2, z3);
            }
        }
        __syncthreads();
        // frag-order writes: 128 (k16,nblk) pairs over 4 warps -> 32 pairs/warp
#pragma unroll
        for (int p8 = 0; p8 < 32; p8++) {
            const int p = wid * 32 + p8;
            const int k16l = p >> 4;     // 0..7  (local k16 within 128-row tile)
            const int nbl  = p & 15;     // 0..15 (local nblk within 128-col tile)
            float v0 = zs[(k16l * 16 + tg +  0) * SZP + nbl * 8 + g];
            float v1 = zs[(k16l * 16 + tg +  4) * SZP + nbl * 8 + g];
            float v2 = zs[(k16l * 16 + tg +  8) * SZP + nbl * 8 + g];
            float v3 = zs[(k16l * 16 + tg + 12) * SZP + nbl * 8 + g];
            const size_t gk16 = (size_t)(bm >> 4) + k16l;
            const size_t gnb  = (size_t)(bn >> 3) + nbl;
            uint4 o = make_uint4(f2tf32(v0), f2tf32(v1), f2tf32(v2), f2tf32(v3));
            *reinterpret_cast<uint4*>(g_Pq + boff + ((gnb * 64 + gk16) * 32 + lane) * 4) = o;
        }
    } else {
#pragma unroll
        for (int mt = 0; mt < 4; mt++) {
#pragma unroll
            for (int nt = 0; nt < 8; nt++) {
                const int row = bm + wm + mt * 16 + g;
                const int col = bn + wn + nt * 8 + 2 * tg;
                const size_t i0 = boff + (size_t)row * D + col;
                const size_t i1 = i0 + (size_t)8 * D;
                const float bv0 = __ldg(bias + col);
                const float bv1 = __ldg(bias + col + 1);
                const float2 q0 = *reinterpret_cast<const float2*>(g_q + i0);
                const float2 q1 = *reinterpret_cast<const float2*>(g_q + i1);
                const float z0 = fmaxf(acc[mt][nt][0] + bv0, 0.0f);
                const float z1 = fmaxf(acc[mt][nt][1] + bv1, 0.0f);
                const float z2 = fmaxf(acc[mt][nt][2] + bv0, 0.0f);
                const float z3 = fmaxf(acc[mt][nt][3] + bv1, 0.0f);
                *reinterpret_cast<float2*>(outp + i0) = make_float2(z0 * q0.x, z1 * q0.y);
                *reinterpret_cast<float2*>(outp + i1) = make_float2(z2 * q1.x, z3 * q1.y);
            }
        }
    }
}

// ---------------- host launcher ----------------
extern "C" void kernel_launch(void* const* d_in, const int* in_sizes, int n_in,
                              void* d_out, int out_size) {
    (void)in_sizes; (void)n_in; (void)out_size;
    // metadata order: K, Q, M, ht, Wp, bp, W3, W4, b3, Wd, bd
    // K / ht / Wd / bd are dead code (scores/softmax deleted in reference).
    const float* Q  = (const float*)d_in[1];
    const float* M  = (const float*)d_in[2];
    const float* Wp = (const float*)d_in[4];
    const float* bp = (const float*)d_in[5];
    const float* W3 = (const float*)d_in[6];
    const float* W4 = (const float*)d_in[7];
    const float* b3 = (const float*)d_in[8];
    float* out = (float*)d_out;

    unsigned* dPA; cudaGetSymbolAddress((void**)&dPA, g_PA);
    unsigned* dPQ; cudaGetSymbolAddress((void**)&dPQ, g_PQ);
    unsigned* dPM; cudaGetSymbolAddress((void**)&dPM, g_PM);
    unsigned* dPq; cudaGetSymbolAddress((void**)&dPq, g_Pq);

    cudaFuncSetAttribute(gemm_tf32<0, 32, 32>, cudaFuncAttributeMaxDynamicSharedMemorySize, SMEM_BYTES);
    cudaFuncSetAttribute(gemm_tf32<1, 64, 32>, cudaFuncAttributeMaxDynamicSharedMemorySize, SMEM_BYTES);

    dim3 gridG(D / BN, D / BM, BATCH);   // (8, 8, 32) = 2048 CTAs
    dim3 blockG(NTHREADS);
    dim3 gB2(1024, 2 * BATCH);           // Q and M in one launch
    dim3 gA(1024, 3);

    permB2_kernel<<<gB2, 256>>>(Q, M, dPQ, dPM);               // [0]
    permA3_kernel<<<gA, 256>>>(Wp, W3, W4, dPA);               // [1]
    // Pass 1: q = Wp @ Q + bp  -> g_q exact + g_Pq frag-order tf32
    gemm_tf32<0, 32, 32><<<gridG, blockG, SMEM_BYTES>>>(dPA, dPQ, dPA, dPQ, bp, nullptr);   // [2]
    // Pass 2: out = relu(W3@M + W4@q + b3) * q  (fused K=2048)
    gemm_tf32<1, 64, 32><<<gridG, blockG, SMEM_BYTES>>>(dPA + (1u << 20), dPM,
                                                        dPA + (2u << 20), dPq, b3, out);    // [3]
}

// round 17
// speedup vs baseline: 1.0015x; 1.0015x over previous
#include <cuda_runtime.h>
#include <cstdint>
#include <cstddef>

// ---------------- problem constants ----------------
#define D      1024
#define BATCH  32
#define NELEM  ((size_t)BATCH * D * D)

// ---------------- tiling ----------------
#define BM 128
#define BN 128
#define BK 32
#define STAGES 3
#define A_STAGE ((BM / 16) * (BK / 8) * 32 * 16)   // 16384 bytes
#define B_STAGE ((BN / 8) * (BK / 16) * 32 * 16)   // 16384 bytes
#define STAGE_BYTES (A_STAGE + B_STAGE)            // 32768
#define SMEM_BYTES (STAGES * STAGE_BYTES)          // 98304 -> 2 CTAs/SM
#define SZP 136                                    // epilogue staging stride (floats)
#define NTHREADS 128

// ---------------- device scratch (allocation-free) ----------------
__device__ __align__(16) unsigned g_PA[3u * 1024 * 1024];   // Wp | W3 | W4 (A-frag tf32)
__device__ __align__(16) unsigned g_PQ[NELEM];              // Q  (B-frag tf32)
__device__ __align__(16) unsigned g_PM[NELEM];              // M  (B-frag tf32)
__device__ __align__(16) unsigned g_Pq[NELEM];              // q  (B-frag tf32)
__device__ __align__(16) float    g_q [NELEM];              // exact q (gate)

// ---------------- helpers ----------------
__device__ __forceinline__ unsigned f2tf32(float x) {
    unsigned r; asm("cvt.rna.tf32.f32 %0, %1;" : "=r"(r) : "f"(x)); return r;
}
__device__ __forceinline__ uint32_t smem_u32(const void* p) {
    uint32_t a;
    asm("{ .reg .u64 t; cvta.to.shared.u64 t, %1; cvt.u32.u64 %0, t; }" : "=r"(a) : "l"(p));
    return a;
}
__device__ __forceinline__ void cp16(uint32_t daddr, const void* src) {
    asm volatile("cp.async.cg.shared.global [%0], [%1], 16;\n" :: "r"(daddr), "l"(src));
}
__device__ __forceinline__ void cp_commit() { asm volatile("cp.async.commit_group;\n" ::); }
__device__ __forceinline__ void cp_wait1()  { asm volatile("cp.async.wait_group 1;\n" ::); }

__device__ __forceinline__ uint4 lds128(uint32_t addr) {
    uint4 v;
    asm volatile("ld.shared.v4.u32 {%0,%1,%2,%3}, [%4];"
                 : "=r"(v.x), "=r"(v.y), "=r"(v.z), "=r"(v.w) : "r"(addr));
    return v;
}
__device__ __forceinline__ void mma_tf32(float c[4], uint4 a, unsigned b0, unsigned b1) {
    asm volatile(
        "mma.sync.aligned.m16n8k8.row.col.f32.tf32.tf32.f32 "
        "{%0,%1,%2,%3}, {%4,%5,%6,%7}, {%8,%9}, {%0,%1,%2,%3};\n"
        : "+f"(c[0]), "+f"(c[1]), "+f"(c[2]), "+f"(c[3])
        : "r"(a.x), "r"(a.y), "r"(a.z), "r"(a.w), "r"(b0), "r"(b1));
}

// ---------------- pre-permutation kernels ----------------
// A-frag order: PA[mblk(64)][kblk(128)][lane(32)][4], tf32 bits. (3 weights fused)
__global__ void permA3_kernel(const float* __restrict__ W0, const float* __restrict__ W1,
                              const float* __restrict__ W2, unsigned* __restrict__ PA) {
    const float* W = (blockIdx.y == 0) ? W0 : (blockIdx.y == 1) ? W1 : W2;
    unsigned* P = PA + ((size_t)blockIdx.y << 20);
    int t = blockIdx.x * blockDim.x + threadIdx.x;
    int lane = t & 31, kblk = (t >> 5) & 127, mblk = t >> 12;
    int g = lane >> 2, tg = lane & 3;
    int m0 = mblk * 16 + g, k0 = kblk * 8 + tg;
    uint4 o;
    o.x = f2tf32(W[(size_t)m0 * D + k0]);
    o.y = f2tf32(W[(size_t)(m0 + 8) * D + k0]);
    o.z = f2tf32(W[(size_t)m0 * D + k0 + 4]);
    o.w = f2tf32(W[(size_t)(m0 + 8) * D + k0 + 4]);
    reinterpret_cast<uint4*>(P)[t] = o;
}

// B-frag order for BOTH Q and M in one launch: grid.y 0..31 -> Q, 32..63 -> M.
__global__ void permB2_kernel(const float* __restrict__ Q, const float* __restrict__ M,
                              unsigned* __restrict__ PQ, unsigned* __restrict__ PM) {
    const int yy = blockIdx.y;
    const int b = yy & 31;
    const float* Xb = ((yy < 32) ? Q : M) + (size_t)b * D * D;
    unsigned* PB = ((yy < 32) ? PQ : PM);
    int t = blockIdx.x * blockDim.x + threadIdx.x;
    int lane = t & 31, k16 = (t >> 5) & 63, nblk = t >> 11;
    int g = lane >> 2, tg = lane & 3;
    int n = nblk * 8 + g, k0 = k16 * 16 + tg;
    uint4 o;
    o.x = f2tf32(Xb[(size_t)k0 * D + n]);
    o.y = f2tf32(Xb[(size_t)(k0 + 4) * D + n]);
    o.z = f2tf32(Xb[(size_t)(k0 + 8) * D + n]);
    o.w = f2tf32(Xb[(size_t)(k0 + 12) * D + n]);
    reinterpret_cast<uint4*>(PB + (size_t)b * D * D)[t] = o;
}

// ---------------- main GEMM ----------------
// 128x128 CTA tile, 4 warps (64x64 each, 2x2 grid), BK=32, 3-stage cp.async,
// 2 CTAs/SM. chunks 0..SPLIT-1 use (A0,B0); SPLIT..KT-1 use (A1,B1).
// MODE 0: g_q = acc + bias (exact); g_Pq = tf32 B-frag order via smem staging
// MODE 1: out = relu(acc + bias) * g_q
template <int MODE, int KT, int SPLIT>
__global__ void __launch_bounds__(NTHREADS, 2)
gemm_tf32(const unsigned* __restrict__ A0, const unsigned* __restrict__ B0,
          const unsigned* __restrict__ A1, const unsigned* __restrict__ B1,
          const float* __restrict__ bias, float* __restrict__ outp) {
    extern __shared__ char smem[];
    const uint32_t sbase = smem_u32(smem);

    const int tid  = threadIdx.x;
    const int lane = tid & 31;
    const int wid  = tid >> 5;     // 0..3

    const int b      = blockIdx.z;
    const int bmblk  = blockIdx.y * (BM / 16);   // 8 mblk per tile
    const int bnblk  = blockIdx.x * (BN / 8);    // 16 nblk per tile
    const size_t boff = (size_t)b * D * D;

    const char* PBb0 = (const char*)(B0 + boff);
    const char* PBb1 = (const char*)(B1 + boff);

    float acc[4][8][4];
#pragma unroll
    for (int mt = 0; mt < 4; mt++)
#pragma unroll
        for (int nt = 0; nt < 8; nt++)
#pragma unroll
            for (int i = 0; i < 4; i++) acc[mt][nt][i] = 0.0f;

    // loader mapping: 128 threads; A = 1024 uint4 (8/thread), B = 1024 uint4 (8/thread)
    auto load_chunk = [&](int c) {
        const int s = c % STAGES;
        const uint32_t sa = sbase + s * STAGE_BYTES;
        const uint32_t sb = sa + A_STAGE;
        const char* Abase; const char* Bbase; int cc;
        if (c < SPLIT) { Abase = (const char*)A0; Bbase = PBb0; cc = c; }
        else           { Abase = (const char*)A1; Bbase = PBb1; cc = c - SPLIT; }
#pragma unroll
        for (int i = 0; i < 8; i++) {
            const unsigned o = tid * 16 + i * 2048;        // byte offset in 16KB A stage
            const int mb = o >> 11;                        // 2KB contiguous per mblk
            const unsigned rest = o & 2047;
            cp16(sa + o, Abase + (((size_t)(bmblk + mb) * 128 + cc * 4) << 9) + rest);
        }
#pragma unroll
        for (int i = 0; i < 8; i++) {
            const unsigned o = tid * 16 + i * 2048;        // byte offset in 16KB B stage
            const int nb = o >> 10;                        // 1KB contiguous per nblk
            const unsigned rest = o & 1023;
            cp16(sb + o, Bbase + (((size_t)(bnblk + nb) * 64 + cc * 2) << 9) + rest);
        }
    };

    const int wm4 = (wid >> 1) * 4;   // mblk base (2 row groups of warps)
    const int wn8 = (wid & 1) * 8;    // nblk base (2 col groups of warps)
    const uint32_t laneoff = lane * 16;

    auto compute_chunk = [&](int c) {
        const uint32_t sa = sbase + (c % STAGES) * STAGE_BYTES;
        const uint32_t sb = sa + A_STAGE;
#pragma unroll
        for (int k16 = 0; k16 < 2; k16++) {
            uint4 bfr[8];
#pragma unroll
            for (int nt = 0; nt < 8; nt++)
                bfr[nt] = lds128(sb + (wn8 + nt) * 1024 + k16 * 512 + laneoff);
#pragma unroll
            for (int half = 0; half < 2; half++) {
                uint4 afr[4];
#pragma unroll
                for (int mt = 0; mt < 4; mt++)
                    afr[mt] = lds128(sa + (wm4 + mt) * 2048 + (k16 * 2 + half) * 512 + laneoff);
#pragma unroll
                for (int nt = 0; nt < 8; nt++) {
                    const unsigned b0 = half ? bfr[nt].z : bfr[nt].x;
                    const unsigned b1 = half ? bfr[nt].w : bfr[nt].y;
#pragma unroll
                    for (int mt = 0; mt < 4; mt++)
                        mma_tf32(acc[mt][nt], afr[mt], b0, b1);
                }
            }
        }
    };

    // prologue: fill 3 stages
    load_chunk(0); cp_commit();
    load_chunk(1); cp_commit();
    load_chunk(2); cp_commit();

    // pair-wise mainloop, 3 stages: compute (c0, c0+1) while c0+2 is in flight
    for (int t = 0; t < KT / 2; t++) {
        const int c0 = 2 * t;
        cp_wait1();            // chunks c0, c0+1 complete (newest group may fly)
        __syncthreads();

        compute_chunk(c0);
        compute_chunk(c0 + 1);

        __syncthreads();       // all warps done reading stages (c0, c0+1)
        if (c0 + 3 < KT) load_chunk(c0 + 3);   // targets stage (c0) % 3
        cp_commit();
        if (c0 + 4 < KT) load_chunk(c0 + 4);   // targets stage (c0+1) % 3
        cp_commit();
    }

    // ---------------- epilogue ----------------
    const int g  = lane >> 2;
    const int tg = lane & 3;
    const int bm = blockIdx.y * BM;
    const int bn = blockIdx.x * BN;
    const int wm = (wid >> 1) * 64;
    const int wn = (wid & 1) * 64;

    if (MODE == 0) {
        // stage z-tile (bias added) into smem; stage buffers are dead now
        __syncthreads();
        float* zs = reinterpret_cast<float*>(smem);   // 128 x SZP floats = 69.6KB < 96KB
#pragma unroll
        for (int mt = 0; mt < 4; mt++) {
#pragma unroll
            for (int nt = 0; nt < 8; nt++) {
                const int rl = wm + mt * 16 + g;
                const int cl = wn + nt * 8 + 2 * tg;
                const int col = bn + cl;
                const float bv0 = __ldg(bias + col);
                const float bv1 = __ldg(bias + col + 1);
                const float z0 = acc[mt][nt][0] + bv0;
                const float z1 = acc[mt][nt][1] + bv1;
                const float z2 = acc[mt][nt][2] + bv0;
                const float z3 = acc[mt][nt][3] + bv1;
                zs[rl * SZP + cl] = z0;
                zs[rl * SZP + cl + 1] = z1;
                zs[(rl + 8) * SZP + cl] = z2;
                zs[(rl + 8) * SZP + cl + 1] = z3;
                // exact q
                const int row = bm + rl;
                const size_t i0 = boff + (size_t)row * D + col;
                const size_t i1 = i0 + (size_t)8 * D;
                *reinterpret_cast<float2*>(g_q + i0) = make_float2(z0, z1);
                *reinterpret_cast<float2*>(g_q + i1) = make_float2(z2, z3);
            }
        }
        __syncthreads();
        // frag-order writes: 128 (k16,nblk) pairs over 4 warps -> 32 pairs/warp
#pragma unroll
        for (int p8 = 0; p8 < 32; p8++) {
            const int p = wid * 32 + p8;
            const int k16l = p >> 4;     // 0..7  (local k16 within 128-row tile)
            const int nbl  = p & 15;     // 0..15 (local nblk within 128-col tile)
            float v0 = zs[(k16l * 16 + tg +  0) * SZP + nbl * 8 + g];
            float v1 = zs[(k16l * 16 + tg +  4) * SZP + nbl * 8 + g];
            float v2 = zs[(k16l * 16 + tg +  8) * SZP + nbl * 8 + g];
            float v3 = zs[(k16l * 16 + tg + 12) * SZP + nbl * 8 + g];
            const size_t gk16 = (size_t)(bm >> 4) + k16l;
            const size_t gnb  = (size_t)(bn >> 3) + nbl;
            uint4 o = make_uint4(f2tf32(v0), f2tf32(v1), f2tf32(v2), f2tf32(v3));
            *reinterpret_cast<uint4*>(g_Pq + boff + ((gnb * 64 + gk16) * 32 + lane) * 4) = o;
        }
    } else {
#pragma unroll
        for (int mt = 0; mt < 4; mt++) {
#pragma unroll
            for (int nt = 0; nt < 8; nt++) {
                const int row = bm + wm + mt * 16 + g;
                const int col = bn + wn + nt * 8 + 2 * tg;
                const size_t i0 = boff + (size_t)row * D + col;
                const size_t i1 = i0 + (size_t)8 * D;
                const float bv0 = __ldg(bias + col);
                const float bv1 = __ldg(bias + col + 1);
                const float2 q0 = *reinterpret_cast<const float2*>(g_q + i0);
                const float2 q1 = *reinterpret_cast<const float2*>(g_q + i1);
                const float z0 = fmaxf(acc[mt][nt][0] + bv0, 0.0f);
                const float z1 = fmaxf(acc[mt][nt][1] + bv1, 0.0f);
                const float z2 = fmaxf(acc[mt][nt][2] + bv0, 0.0f);
                const float z3 = fmaxf(acc[mt][nt][3] + bv1, 0.0f);
                *reinterpret_cast<float2*>(outp + i0) = make_float2(z0 * q0.x, z1 * q0.y);
                *reinterpret_cast<float2*>(outp + i1) = make_float2(z2 * q1.x, z3 * q1.y);
            }
        }
    }
}

// ---------------- host launcher ----------------
extern "C" void kernel_launch(void* const* d_in, const int* in_sizes, int n_in,
                              void* d_out, int out_size) {
    (void)in_sizes; (void)n_in; (void)out_size;
    // metadata order: K, Q, M, ht, Wp, bp, W3, W4, b3, Wd, bd
    // K / ht / Wd / bd are dead code (scores/softmax deleted in reference).
    const float* Q  = (const float*)d_in[1];
    const float* M  = (const float*)d_in[2];
    const float* Wp = (const float*)d_in[4];
    const float* bp = (const float*)d_in[5];
    const float* W3 = (const float*)d_in[6];
    const float* W4 = (const float*)d_in[7];
    const float* b3 = (const float*)d_in[8];
    float* out = (float*)d_out;

    unsigned* dPA; cudaGetSymbolAddress((void**)&dPA, g_PA);
    unsigned* dPQ; cudaGetSymbolAddress((void**)&dPQ, g_PQ);
    unsigned* dPM; cudaGetSymbolAddress((void**)&dPM, g_PM);
    unsigned* dPq; cudaGetSymbolAddress((void**)&dPq, g_Pq);

    cudaFuncSetAttribute(gemm_tf32<0, 32, 32>, cudaFuncAttributeMaxDynamicSharedMemorySize, SMEM_BYTES);
    cudaFuncSetAttribute(gemm_tf32<1, 64, 32>, cudaFuncAttributeMaxDynamicSharedMemorySize, SMEM_BYTES);

    dim3 gridG(D / BN, D / BM, BATCH);   // (8, 8, 32) = 2048 CTAs
    dim3 blockG(NTHREADS);
    dim3 gB2(1024, 2 * BATCH);           // Q and M in one launch
    dim3 gA(1024, 3);

    permB2_kernel<<<gB2, 256>>>(Q, M, dPQ, dPM);               // [0]
    permA3_kernel<<<gA, 256>>>(Wp, W3, W4, dPA);               // [1]
    // Pass 1: q = Wp @ Q + bp  -> g_q exact + g_Pq frag-order tf32
    gemm_tf32<0, 32, 32><<<gridG, blockG, SMEM_BYTES>>>(dPA, dPQ, dPA, dPQ, bp, nullptr);   // [2]
    // Pass 2: out = relu(W3@M + W4@q + b3) * q  (fused K=2048)
    gemm_tf32<1, 64, 32><<<gridG, blockG, SMEM_BYTES>>>(dPA + (1u << 20), dPM,
                                                        dPA + (2u << 20), dPq, b3, out);    // [3]
}